// round 14
// baseline (speedup 1.0000x reference)
#include <cuda_runtime.h>

// MaxPool2d k=2 s=2 valid, (32,64,224,224) fp32 -> (32,64,112,112).
// R13 = compose the two independently-proven wins:
//   (a) R12 per-instruction coalescing: all loads lane-consecutive -> each
//       warp LDG.128 covers one contiguous 512 B (4 full lines, L1 23%).
//   (b) R3 depth: 8 front-batched independent loads in ONE batch (no
//       mid-thread consumption point) for deeper per-thread MLP.
// One thread = 4 output rows x 2 output cols: 8 LDG.128 from input rows
// 8q..8q+7 at the same float4 column, 4 STG.64 (256 B contiguous per warp).
// Plain cache ops (best measured). All accesses aligned.

#define NC_TOTAL   2048              // 32 * 64
#define IH         224
#define IW         224
#define OH         112
#define OW         112
#define IN_PLANE   (IH * IW)         // 50176
#define OUT_PLANE  (OH * OW)         // 12544
#define GROUPS_W   (IW / 4)          // 56 float4 columns (= 2 output cols each)
#define ROWQUADS   (OH / 4)          // 28 quads of output rows
#define TOTAL_THREADS (NC_TOTAL * ROWQUADS * GROUPS_W)   // 3,211,264

__device__ __forceinline__ float2 pool_row(const float4 a, const float4 b) {
    float2 o;
    o.x = fmaxf(fmaxf(a.x, a.y), fmaxf(b.x, b.y));
    o.y = fmaxf(fmaxf(a.z, a.w), fmaxf(b.z, b.w));
    return o;
}

__global__ __launch_bounds__(256)
void maxpool2d_k2s2_coal8_kernel(const float* __restrict__ in, float* __restrict__ out) {
    int idx = blockIdx.x * blockDim.x + threadIdx.x;
    if (idx >= TOTAL_THREADS) return;

    int g   = idx % GROUPS_W;            // float4 column (4 input cols -> 2 out cols)
    int t   = idx / GROUPS_W;
    int q   = t % ROWQUADS;              // which quad of output rows
    int nc  = t / ROWQUADS;

    const int rstep = IW / 4;            // 56 float4 per input row
    const float4* base = reinterpret_cast<const float4*>(
        in + (size_t)nc * IN_PLANE + (size_t)(q * 8) * IW) + g;

    // Single front batch of 8 independent, per-instruction fully coalesced loads.
    float4 a = base[0 * rstep];
    float4 b = base[1 * rstep];
    float4 c = base[2 * rstep];
    float4 d = base[3 * rstep];
    float4 e = base[4 * rstep];
    float4 f = base[5 * rstep];
    float4 gg = base[6 * rstep];
    float4 h = base[7 * rstep];

    float2* orow = reinterpret_cast<float2*>(
        out + (size_t)nc * OUT_PLANE + (size_t)(q * 4) * OW) + g;
    const int ostep = OW / 2;            // 56 float2 per output row

    orow[0 * ostep] = pool_row(a, b);
    orow[1 * ostep] = pool_row(c, d);
    orow[2 * ostep] = pool_row(e, f);
    orow[3 * ostep] = pool_row(gg, h);
}

extern "C" void kernel_launch(void* const* d_in, const int* in_sizes, int n_in,
                              void* d_out, int out_size) {
    const float* in = (const float*)d_in[0];
    float* out = (float*)d_out;
    int blocks = (TOTAL_THREADS + 255) / 256;   // 12544
    maxpool2d_k2s2_coal8_kernel<<<blocks, 256>>>(in, out);
}